// round 16
// baseline (speedup 1.0000x reference)
#include <cuda_runtime.h>
#include <cuda_fp16.h>
#include <math.h>
#include <stdint.h>

#define BTn 512
#define En  512
#define Hn  1024
#define Gn  4096
#define NCn 33
#define VBn 32
#define NSTEPS 128
#define KC 128
#define NCTA 128
#define NTHR 512
#define LSCALE 4194304.0f
#define LINV   2.384185791015625e-07f

// ============================ device globals ============================
__device__ __align__(256) float d_cond[BTn*Hn];
__device__ __align__(256) float d_condG0p[BTn*Gn];   // quad layout: [r][jh*4 + gate]
__device__ __align__(256) float d_bvecM[3*Gn];        // quad: bvec | M2row0 | M2row1
__device__ __align__(256) float d_b1p[Gn];            // quad bih1+bhh1
__device__ __align__(256) __half d_Whh0h[Gn*Hn];
__device__ __align__(256) __half d_Wih1h[Gn*Hn];
__device__ __align__(256) __half d_Whh1h[Gn*Hn];
__device__ __align__(256) __half d_h0h[2][BTn*Hn];    // [step parity]
__device__ __align__(256) __half d_h1h[2][BTn*Hn];
__device__ __align__(256) float d_cur[BTn*2];
__device__ __align__(256) int d_intbuf[2][BTn*NCn];   // fixed-point logit partial sums
__device__ __align__(256) unsigned d_cntb[4][64];     // per-band arrival counters (256B apart)
__device__ unsigned d_cntg;                            // global (band-last) counter
__device__ unsigned d_flag;

__device__ __forceinline__ float fast_sig(float x){
  float e; asm("ex2.approx.f32 %0, %1;" : "=f"(e) : "f"(-1.4426950408889634f*x));
  float r; asm("rcp.approx.f32 %0, %1;" : "=f"(r) : "f"(1.f+e));
  return r;
}
__device__ __forceinline__ float fast_tanh(float x){
  float e; asm("ex2.approx.f32 %0, %1;" : "=f"(e) : "f"(-2.885390081777927f*x));
  float r; asm("rcp.approx.f32 %0, %1;" : "=f"(r) : "f"(1.f+e));
  return fmaf(2.f, r, -1.f);
}

__device__ __forceinline__ uint32_t smem_u32(const void* p){
  uint32_t a; asm("{ .reg .u64 t; cvta.to.shared.u64 t, %1; cvt.u32.u64 %0, t; }" : "=r"(a) : "l"(p));
  return a;
}

#define MMA16816(d, a, b) \
  asm volatile("mma.sync.aligned.m16n8k16.row.col.f32.f16.f16.f32 " \
    "{%0,%1,%2,%3}, {%4,%5,%6,%7}, {%8,%9}, {%0,%1,%2,%3};" \
    : "+f"((d)[0]), "+f"((d)[1]), "+f"((d)[2]), "+f"((d)[3]) \
    : "r"((a)[0]), "r"((a)[1]), "r"((a)[2]), "r"((a)[3]), "r"((b)[0]), "r"((b)[1]))

// ---- hierarchical grid barrier: band counters -> global counter -> flag ----
__device__ __forceinline__ unsigned atom_acqrel_add1(unsigned* p){
  unsigned o;
  asm volatile("atom.acq_rel.gpu.global.add.u32 %0, [%1], 1;" : "=r"(o) : "l"(p) : "memory");
  return o;
}
__device__ __forceinline__ void gridbar(int band, unsigned target){
  __syncthreads();
  if (threadIdx.x == 0){
    __threadfence();
    int released = 0;
    unsigned ob = atom_acqrel_add1(&d_cntb[band][0]);
    if (ob == target*32u - 1u){
      unsigned og = atom_acqrel_add1(&d_cntg);
      if (og == target*4u - 1u){
        asm volatile("st.release.gpu.u32 [%0], %1;" :: "l"(&d_flag), "r"(target) : "memory");
        released = 1;
      }
    }
    if (!released){
      unsigned v;
      do { asm volatile("ld.acquire.gpu.u32 %0, [%1];" : "=r"(v) : "l"(&d_flag) : "memory"); }
      while (v < target);
    }
  }
  __syncthreads();
}

// ============================ init ============================
__global__ void k_init(const float* __restrict__ sos){
  int idx = blockIdx.x*blockDim.x + threadIdx.x;
  if (idx < BTn*Hn){
    __half z = __float2half(0.f);
    d_h0h[0][idx]=z; d_h0h[1][idx]=z; d_h1h[0][idx]=z; d_h1h[1][idx]=z;
  }
  if (idx < BTn){ d_cur[idx*2+0]=sos[0]; d_cur[idx*2+1]=sos[1]; }
  if (idx < 2*BTn*NCn) ((int*)d_intbuf)[idx] = 0;
  if (idx < 4*64) ((unsigned*)d_cntb)[idx] = 0u;
  if (idx == 0){ d_cntg = 0u; d_flag = 0u; }
}

// ============ weight convert: transpose + pcol2 permute + fp16 ============
__global__ void k_wconv(const float* __restrict__ W0, const float* __restrict__ W1,
                        const float* __restrict__ W2){
  __shared__ float ts[64][65];
  const float* W = (blockIdx.z==0)? W0 : (blockIdx.z==1)? W1 : W2;
  __half* Dhi = (blockIdx.z==0)? d_Whh0h : (blockIdx.z==1)? d_Wih1h : d_Whh1h;
  int c0 = blockIdx.x*64, k0 = blockIdx.y*64;
  int tx = threadIdx.x, ty = threadIdx.y;
  #pragma unroll
  for (int i=0;i<8;i++){
    int kl = ty + i*8;
    ts[kl][tx] = W[(size_t)(k0+kl)*Gn + c0 + tx];
  }
  __syncthreads();
  #pragma unroll
  for (int i=0;i<8;i++){
    int lc = ty + i*8;
    int c = c0 + lc;
    int q = c >> 10, jh = c & 1023;
    int pcol = ((q>>1)<<11) | (jh<<1) | (q&1);
    Dhi[(size_t)pcol*Hn + k0 + tx] = __float2half_rn(ts[tx][lc]);
  }
}

// ======== bvec/M2/b1 precompute (quad layout: jh*4+gate) ========
__global__ void k_prep(const float* __restrict__ Wih0, const float* __restrict__ bi,
                       const float* __restrict__ Wi,   const float* __restrict__ bih0,
                       const float* __restrict__ bhh0, const float* __restrict__ bih1,
                       const float* __restrict__ bhh1){
  int j = blockIdx.x*blockDim.x + threadIdx.x;
  float ab=0.f, a0=0.f, a1=0.f;
  for (int k=0;k<Hn;k++){
    float w = Wih0[(size_t)k*Gn + j];
    ab = fmaf(bi[k],    w, ab);
    a0 = fmaf(Wi[k],    w, a0);
    a1 = fmaf(Wi[Hn+k], w, a1);
  }
  int pcol = ((j & 1023) << 2) | (j >> 10);
  d_bvecM[pcol]        = bih0[j] + bhh0[j] + ab;
  d_bvecM[Gn+pcol]     = a0;
  d_bvecM[2*Gn+pcol]   = a1;
  d_b1p[pcol]          = bih1[j] + bhh1[j];
}

// ============ one-time fp32 GEMM (cond and condG0p) ============
#define AS_LD 132
template<int MODE>
__global__ __launch_bounds__(256) void gemm128(const float* __restrict__ Aext,
    const float* __restrict__ W, const float* __restrict__ biasExt, int N, int K)
{
  __shared__ float As[16*AS_LD];
  __shared__ float Ws[16*AS_LD];
  const int m0 = blockIdx.y*128, n0 = blockIdx.x*128;
  const int tid = threadIdx.x;
  const int trow = tid>>4, tcol = tid&15;
  float acc[8][8];
  #pragma unroll
  for(int i=0;i<8;i++){
    #pragma unroll
    for(int j=0;j<8;j++) acc[i][j]=0.f;
  }
  const float* Ap = MODE ? d_cond : Aext;
  for (int k0=0;k0<K;k0+=16){
    #pragma unroll
    for (int i=0;i<2;i++){
      int f = tid + i*256;
      int r = f>>2, c = f&3;
      float4 v = *(const float4*)(Ap + (size_t)(m0+r)*K + k0 + c*4);
      As[(c*4+0)*AS_LD + r]=v.x; As[(c*4+1)*AS_LD + r]=v.y;
      As[(c*4+2)*AS_LD + r]=v.z; As[(c*4+3)*AS_LD + r]=v.w;
    }
    #pragma unroll
    for (int i=0;i<2;i++){
      int f = tid + i*256;
      int kr = f>>5, nc = f&31;
      *(float4*)(&Ws[kr*AS_LD + nc*4]) = *(const float4*)(W + (size_t)(k0+kr)*N + n0 + nc*4);
    }
    __syncthreads();
    #pragma unroll
    for (int kk=0;kk<16;kk++){
      float a[8], b[8];
      *(float4*)(a)   = *(const float4*)(&As[kk*AS_LD + trow*8]);
      *(float4*)(a+4) = *(const float4*)(&As[kk*AS_LD + trow*8+4]);
      *(float4*)(b)   = *(const float4*)(&Ws[kk*AS_LD + tcol*8]);
      *(float4*)(b+4) = *(const float4*)(&Ws[kk*AS_LD + tcol*8+4]);
      #pragma unroll
      for(int i=0;i<8;i++){
        #pragma unroll
        for(int j=0;j<8;j++) acc[i][j] = fmaf(a[i], b[j], acc[i][j]);
      }
    }
    __syncthreads();
  }
  #pragma unroll
  for (int i=0;i<8;i++){
    int r = m0 + trow*8 + i;
    #pragma unroll
    for (int j=0;j<8;j++){
      int col = n0 + tcol*8 + j;
      float v = acc[i][j];
      if (MODE==0){
        v += biasExt[col];
        d_cond[(size_t)r*N + col] = v;
      } else {
        int pcol = ((col & 1023) << 2) | (col >> 10);
        v += d_bvecM[pcol];
        d_condG0p[(size_t)r*N + pcol] = v;
      }
    }
  }
}

// ============================ persistent step kernel ============================
#define STAGE_BYTES 65536
#define NSTAGE 3
#define SM_CUR (NSTAGE*STAGE_BYTES)
#define SM_WO  (SM_CUR + 1024)
#define SM_BO  (SM_WO + 4352)
#define GEMM_SMEM (SM_BO + 256)

__device__ __forceinline__ void load_stage(uint32_t sbase, const __half* Asrc,
    const __half* Whi, int m0, int nb, int k0, int tid){
  #pragma unroll
  for (int it=0; it<8; it++){
    int idx = it*NTHR + tid;
    int tile = idx >> 11;
    int rem  = idx & 2047;
    int row  = rem >> 4;
    int cc   = rem & 15;
    const __half* src;
    if (tile==0) src = Asrc + (size_t)(m0+row)*Hn;
    else {
      int pr = nb*64 + row + ((row>=64)? (2048-64) : 0);
      src = Whi + (size_t)pr*Hn;
    }
    uint32_t daddr = sbase + tile*32768 + row*256 + ((cc ^ (row&7))<<4);
    const void* g = (const void*)(src + k0 + cc*8);
    asm volatile("cp.async.cg.shared.global [%0], [%1], 16;" :: "r"(daddr), "l"(g));
  }
}

__device__ __forceinline__ void compute_stage(uint32_t sbase, float acc[2][4][4],
                                              int lane, int wm, int wn){
  const uint32_t As = sbase, Bh = sbase + 32768;
  #pragma unroll
  for (int kk=0; kk<8; kk++){
    uint32_t a[2][4];
    #pragma unroll
    for (int mt=0; mt<2; mt++){
      int m = wm*32 + mt*16 + (lane & 15);
      int ch = kk*2 + (lane>>4);
      uint32_t addr = As + m*256 + ((ch ^ (m&7))<<4);
      asm volatile("ldmatrix.sync.aligned.m8n8.x4.shared.b16 {%0,%1,%2,%3}, [%4];"
        : "=r"(a[mt][0]),"=r"(a[mt][1]),"=r"(a[mt][2]),"=r"(a[mt][3]) : "r"(addr));
    }
    uint32_t bh[4][2];
    #pragma unroll
    for (int np=0; np<2; np++){
      int mat = lane >> 3;
      int ntl = np*2 + (mat>>1);
      int ch  = kk*2 + (mat&1);
      int rb = (ntl<2 ? wn*16 + ntl*8 : 64 + wn*16 + (ntl-2)*8) + (lane&7);
      uint32_t addr = Bh + rb*256 + ((ch ^ (rb&7))<<4);
      uint32_t r0,r1,r2,r3;
      asm volatile("ldmatrix.sync.aligned.m8n8.x4.shared.b16 {%0,%1,%2,%3}, [%4];"
        : "=r"(r0),"=r"(r1),"=r"(r2),"=r"(r3) : "r"(addr));
      bh[np*2+0][0]=r0; bh[np*2+0][1]=r1;
      bh[np*2+1][0]=r2; bh[np*2+1][1]=r3;
    }
    #pragma unroll
    for (int mt=0; mt<2; mt++){
      #pragma unroll
      for (int nt=0; nt<4; nt++){
        MMA16816(acc[mt][nt], a[mt], bh[nt]);
      }
    }
  }
}

// L0: ch 0-7 = h0_prev@Whh0
// L1: ch 0-7 = h1_prev@Whh1 (hoistable), ch 8-15 = h0(s)@Wih1 (post-barrier)
template<int LAYER>
__device__ __forceinline__ void chunk_src(int sbuf, int ch, const __half*& A,
    const __half*& Wh, int& k0){
  if (LAYER==0){ A = d_h0h[sbuf^1]; Wh = d_Whh0h; k0 = ch*KC; }
  else if (ch < 8){ A = d_h1h[sbuf^1]; Wh = d_Whh1h; k0 = ch*KC; }
  else { A = d_h0h[sbuf]; Wh = d_Wih1h; k0 = (ch-8)*KC; }
}

// PROLOG_DONE: if 1, stages 0-1 were already filled+committed by caller
template<int LAYER, int PROLOG_DONE>
__device__ __forceinline__ void gemm_phase(char* smem, uint32_t sb, int sbuf, int nb, int m0,
    int tid, int lane, int wid, const float* curbuf, const float* wo_s, float* creg){
  const int wm = wid >> 2, wn = wid & 3;
  const int nch = LAYER ? 16 : 8;

  float acc[2][4][4];
  #pragma unroll
  for (int i=0;i<2;i++){
    #pragma unroll
    for (int j=0;j<4;j++){
      #pragma unroll
      for (int k=0;k<4;k++) acc[i][j][k]=0.f;
    }
  }

  if (!PROLOG_DONE){
    #pragma unroll
    for (int p=0;p<2;p++){
      const __half *A, *Wh; int k0;
      chunk_src<LAYER>(sbuf, p, A, Wh, k0);
      load_stage(sb + p*STAGE_BYTES, A, Wh, m0, nb, k0, tid);
      asm volatile("cp.async.commit_group;");
    }
  }
  for (int ch=0; ch<nch; ch++){
    asm volatile("cp.async.wait_group 1;");
    __syncthreads();
    if (ch+2 < nch){
      const __half *A, *Wh; int k0;
      chunk_src<LAYER>(sbuf, ch+2, A, Wh, k0);
      load_stage(sb + ((ch+2)%NSTAGE)*STAGE_BYTES, A, Wh, m0, nb, k0, tid);
    }
    asm volatile("cp.async.commit_group;");
    compute_stage(sb + (ch%NSTAGE)*STAGE_BYTES, acc, lane, wm, wn);
  }
  asm volatile("cp.async.wait_group 0;");
  __syncthreads();

  // ---- fused LSTM cell epilogue (warp: 32 rows x 32 cols), c in registers ----
  const int q  = lane & 3;
  const int tq = lane >> 2;
  __half* hout = LAYER ? d_h1h[sbuf] : d_h0h[sbuf];
  float* hbuf = (float*)smem;    // stage0 region reuse (L1 only)

  #pragma unroll
  for (int mt=0; mt<2; mt++){
    #pragma unroll
    for (int rr=0; rr<2; rr++){
      int lr = wm*32 + mt*16 + tq + rr*8;
      int r = m0 + lr;
      float cu0 = 0.f, cu1 = 0.f;
      if (LAYER == 0){ cu0 = curbuf[2*lr]; cu1 = curbuf[2*lr+1]; }
      #pragma unroll
      for (int nt=0; nt<2; nt++){
        int cloc = wn*8 + nt*4 + q;
        int jh = nb*32 + cloc;
        int ci = mt*4 + rr*2 + nt;
        float vi = acc[mt][nt  ][rr*2+0];
        float vf = acc[mt][nt  ][rr*2+1];
        float vg = acc[mt][nt+2][rr*2+0];
        float vo = acc[mt][nt+2][rr*2+1];
        if (LAYER == 0){
          float4 pg = *(const float4*)&d_condG0p[(size_t)r*Gn + jh*4];
          float4 ma = *(const float4*)&d_bvecM[Gn + jh*4];
          float4 mb = *(const float4*)&d_bvecM[2*Gn + jh*4];
          vi += pg.x + cu0*ma.x + cu1*mb.x;
          vf += pg.y + cu0*ma.y + cu1*mb.y;
          vg += pg.z + cu0*ma.z + cu1*mb.z;
          vo += pg.w + cu0*ma.w + cu1*mb.w;
        } else {
          float4 b1 = *(const float4*)&d_b1p[jh*4];
          vi += b1.x; vf += b1.y; vg += b1.z; vo += b1.w;
        }
        float cn = fast_sig(vf)*creg[ci] + fast_sig(vi)*fast_tanh(vg);
        creg[ci] = cn;
        float h = fast_sig(vo)*fast_tanh(cn);
        hout[(size_t)r*Hn + jh] = __float2half_rn(h);
        if (LAYER) hbuf[lr*33 + cloc] = h;
      }
    }
  }

  // ---- L1: partial logits over this CTA's 32 columns, int atomics ----
  if (LAYER == 1){
    __syncthreads();
    const int lr = tid >> 2, qt = tid & 3;   // 4 threads per row
    float pacc[NCn];
    #pragma unroll
    for (int c=0;c<NCn;c++) pacc[c]=0.f;
    const float* hb = hbuf + lr*33;
    #pragma unroll
    for (int cc2=0; cc2<8; cc2++){
      int col = qt*8 + cc2;
      float h = hb[col];
      const float* wr = wo_s + col*34;
      #pragma unroll
      for (int o=0;o<NCn;o++) pacc[o] = fmaf(h, wr[o], pacc[o]);
    }
    int* ob = &d_intbuf[sbuf][(m0+lr)*NCn];
    #pragma unroll
    for (int o=0;o<NCn;o++){
      float v = pacc[o];
      v += __shfl_xor_sync(0xffffffffu, v, 1);
      v += __shfl_xor_sync(0xffffffffu, v, 2);
      if (qt == 0) atomicAdd(&ob[o], __float2int_rn(v*LSCALE));
    }
  }
}

__global__ __launch_bounds__(NTHR, 1) void k_steps(const float* __restrict__ Wo,
    const float* __restrict__ bo, float* __restrict__ out){
  extern __shared__ char smem[];
  const uint32_t sb = smem_u32(smem);
  float* curbuf = (float*)(smem + SM_CUR);
  float* wo_s   = (float*)(smem + SM_WO);
  float* bos    = (float*)(smem + SM_BO);
  const int tid = threadIdx.x;
  const int lane = tid & 31, wid = tid >> 5;
  const int cta = blockIdx.x;
  const int nb = cta & 31, m0 = (cta >> 5) * 128;
  const int band = cta >> 5;

  for (int i=tid; i<32*NCn; i+=NTHR){
    int col = i/NCn, c = i - col*NCn;
    wo_s[col*34+c] = Wo[(size_t)(nb*32+col)*NCn + c];
  }
  if (tid < NCn) bos[tid] = bo[tid];
  __syncthreads();

  // register-resident cell state (this thread's 8 cells per layer, all steps)
  float c0r[8], c1r[8];
  #pragma unroll
  for (int i=0;i<8;i++){ c0r[i]=0.f; c1r[i]=0.f; }

  unsigned bar = 0;
  for (int s=0; s<NSTEPS; s++){
    const int sbuf = s & 1;
    // ---- cur compute for this band (warps 0-3) ----
    if (tid < 128){
      int r = m0 + tid;
      float cu0, cu1;
      if (s == 0){
        cu0 = d_cur[2*r]; cu1 = d_cur[2*r+1];
      } else {
        const int* ib = &d_intbuf[(s-1)&1][r*NCn];
        float lg0 = (float)ib[0]*LINV + bos[0];
        float best = -3.4e38f; int bidx = 0;
        #pragma unroll
        for (int c=1;c<NCn;c++){
          float v = (float)ib[c]*LINV + bos[c];
          if (v > best){ best = v; bidx = c-1; }
        }
        cu0 = (lg0 > 0.f) ? 1.f : 0.f;
        cu1 = (float)bidx * (1.f/(VBn-1));
      }
      curbuf[tid*2] = cu0; curbuf[tid*2+1] = cu1;
    }
    // ---- distributed out writes for step s-1 (warps 8-11, concurrent) ----
    if (s > 0 && tid >= 256 && tid < 388){
      int t2 = tid - 256;
      int r = m0 + nb*4 + t2/33;
      int c = t2 - (t2/33)*33;
      float v = (float)d_intbuf[(s-1)&1][r*NCn + c]*LINV + bos[c];
      int b = r>>6, tt = r&63;
      out[(((size_t)b*NCn + c)*64 + tt)*128 + (s-1)] = v;
    }
    __syncthreads();
    if (s == 0){
      gemm_phase<0,0>(smem, sb, sbuf, nb, m0, tid, lane, wid, curbuf, wo_s, c0r);
    } else {
      gemm_phase<0,1>(smem, sb, sbuf, nb, m0, tid, lane, wid, curbuf, wo_s, c0r);
    }

    // ---- hoisted L1 prologue (chunks 0-1 = h1_prev@Whh1; prev-step sources) ----
    #pragma unroll
    for (int p=0;p<2;p++){
      const __half *A, *Wh; int k0;
      chunk_src<1>(sbuf, p, A, Wh, k0);
      load_stage(sb + p*STAGE_BYTES, A, Wh, m0, nb, k0, tid);
      asm volatile("cp.async.commit_group;");
    }
    gridbar(band, ++bar);
    if (tid < 132) d_intbuf[sbuf ^ 1][cta*132 + tid] = 0;
    gemm_phase<1,1>(smem, sb, sbuf, nb, m0, tid, lane, wid, curbuf, wo_s, c1r);

    // ---- hoisted L0(s+1) prologue: sources synced at mid-step barrier ----
    if (s + 1 < NSTEPS){
      __syncthreads();   // all threads done reading hbuf (aliases stage 0)
      #pragma unroll
      for (int p=0;p<2;p++){
        const __half *A, *Wh; int k0;
        chunk_src<0>((s+1)&1, p, A, Wh, k0);
        load_stage(sb + p*STAGE_BYTES, A, Wh, m0, nb, k0, tid);
        asm volatile("cp.async.commit_group;");
      }
    }
    gridbar(band, ++bar);
  }
  // final out for s = 127 (distributed: 4 rows per CTA)
  if (tid < 132){
    int r = m0 + nb*4 + tid/33;
    int c = tid - (tid/33)*33;
    float v = (float)d_intbuf[1][r*NCn + c]*LINV + bos[c];
    int b = r>>6, tt = r&63;
    out[(((size_t)b*NCn + c)*64 + tt)*128 + 127] = v;
  }
}

// ============================ launch ============================
extern "C" void kernel_launch(void* const* d_in, const int* in_sizes, int n_in,
                              void* d_out, int out_size){
  const float* x    = (const float*)d_in[0];
  const float* sos  = (const float*)d_in[1];
  const float* Wc   = (const float*)d_in[2];
  const float* bc   = (const float*)d_in[3];
  const float* Wi   = (const float*)d_in[4];
  const float* bi   = (const float*)d_in[5];
  const float* Wih0 = (const float*)d_in[6];
  const float* Whh0 = (const float*)d_in[7];
  const float* bih0 = (const float*)d_in[8];
  const float* bhh0 = (const float*)d_in[9];
  const float* Wih1 = (const float*)d_in[10];
  const float* Whh1 = (const float*)d_in[11];
  const float* bih1 = (const float*)d_in[12];
  const float* bhh1 = (const float*)d_in[13];
  const float* Wo   = (const float*)d_in[14];
  const float* bo   = (const float*)d_in[15];
  float* out = (float*)d_out;

  cudaFuncSetAttribute(k_steps, cudaFuncAttributeMaxDynamicSharedMemorySize, GEMM_SMEM);

  k_init<<<(BTn*Hn+255)/256, 256>>>(sos);
  k_wconv<<<dim3(Gn/64, Hn/64, 3), dim3(64,8)>>>(Whh0, Wih1, Whh1);
  k_prep<<<Gn/128, 128>>>(Wih0, bi, Wi, bih0, bhh0, bih1, bhh1);
  gemm128<0><<<dim3(Hn/128, BTn/128), 256>>>(x, Wc, bc, Hn, En);
  gemm128<1><<<dim3(Gn/128, BTn/128), 256>>>(nullptr, Wih0 + (size_t)Hn*Gn, nullptr, Gn, Hn);

  k_steps<<<NCTA, NTHR, GEMM_SMEM>>>(Wo, bo, out);
}

// round 17
// speedup vs baseline: 1.0598x; 1.0598x over previous
#include <cuda_runtime.h>
#include <cuda_fp16.h>
#include <math.h>
#include <stdint.h>

#define BTn 512
#define En  512
#define Hn  1024
#define Gn  4096
#define NCn 33
#define VBn 32
#define NSTEPS 128
#define KC 128
#define NCTA 128
#define NTHR 512
#define LSCALE 4194304.0f
#define LINV   2.384185791015625e-07f

// ============================ device globals ============================
__device__ __align__(256) float d_cond[BTn*Hn];
__device__ __align__(256) float d_condG0p[BTn*Gn];   // quad layout: [r][jh*4 + gate]
__device__ __align__(256) float d_bvecM[3*Gn];        // quad: bvec | M2row0 | M2row1
__device__ __align__(256) float d_b1p[Gn];            // quad bih1+bhh1
__device__ __align__(256) __half d_Whh0h[Gn*Hn];
__device__ __align__(256) __half d_Wih1h[Gn*Hn];
__device__ __align__(256) __half d_Whh1h[Gn*Hn];
__device__ __align__(256) __half d_h0h[2][BTn*Hn];    // [step parity]
__device__ __align__(256) __half d_h1h[2][BTn*Hn];
__device__ __align__(256) float d_cur[BTn*2];
__device__ __align__(256) int d_intbuf[2][BTn*NCn];   // fixed-point logit partial sums
__device__ __align__(256) unsigned d_cnt4[4][64];     // per-band counter (256B apart)
__device__ __align__(256) unsigned d_flag4[4][64];    // per-band flag (256B apart)

__device__ __forceinline__ float fast_sig(float x){
  float e; asm("ex2.approx.f32 %0, %1;" : "=f"(e) : "f"(-1.4426950408889634f*x));
  float r; asm("rcp.approx.f32 %0, %1;" : "=f"(r) : "f"(1.f+e));
  return r;
}
__device__ __forceinline__ float fast_tanh(float x){
  float e; asm("ex2.approx.f32 %0, %1;" : "=f"(e) : "f"(-2.885390081777927f*x));
  float r; asm("rcp.approx.f32 %0, %1;" : "=f"(r) : "f"(1.f+e));
  return fmaf(2.f, r, -1.f);
}

__device__ __forceinline__ uint32_t smem_u32(const void* p){
  uint32_t a; asm("{ .reg .u64 t; cvta.to.shared.u64 t, %1; cvt.u32.u64 %0, t; }" : "=r"(a) : "l"(p));
  return a;
}

#define MMA16816(d, a, b) \
  asm volatile("mma.sync.aligned.m16n8k16.row.col.f32.f16.f16.f32 " \
    "{%0,%1,%2,%3}, {%4,%5,%6,%7}, {%8,%9}, {%0,%1,%2,%3};" \
    : "+f"((d)[0]), "+f"((d)[1]), "+f"((d)[2]), "+f"((d)[3]) \
    : "r"((a)[0]), "r"((a)[1]), "r"((a)[2]), "r"((a)[3]), "r"((b)[0]), "r"((b)[1]))

// ---- band-local barrier (32 CTAs), flat protocol identical to R15 ----
__device__ __forceinline__ void gridbar(int band, unsigned target){
  __syncthreads();
  if (threadIdx.x == 0){
    __threadfence();
    unsigned old = atomicAdd(&d_cnt4[band][0], 1u);
    if (old == target*32u - 1u){
      asm volatile("st.release.gpu.u32 [%0], %1;" :: "l"(&d_flag4[band][0]), "r"(target) : "memory");
    } else {
      unsigned v;
      do { asm volatile("ld.acquire.gpu.u32 %0, [%1];" : "=r"(v) : "l"(&d_flag4[band][0]) : "memory"); }
      while (v < target);
    }
  }
  __syncthreads();
}

// ============================ init ============================
__global__ void k_init(const float* __restrict__ sos){
  int idx = blockIdx.x*blockDim.x + threadIdx.x;
  if (idx < BTn*Hn){
    __half z = __float2half(0.f);
    d_h0h[0][idx]=z; d_h0h[1][idx]=z; d_h1h[0][idx]=z; d_h1h[1][idx]=z;
  }
  if (idx < BTn){ d_cur[idx*2+0]=sos[0]; d_cur[idx*2+1]=sos[1]; }
  if (idx < 2*BTn*NCn) ((int*)d_intbuf)[idx] = 0;
  if (idx < 4*64){ ((unsigned*)d_cnt4)[idx] = 0u; ((unsigned*)d_flag4)[idx] = 0u; }
}

// ============ weight convert: transpose + pcol2 permute + fp16 ============
__global__ void k_wconv(const float* __restrict__ W0, const float* __restrict__ W1,
                        const float* __restrict__ W2){
  __shared__ float ts[64][65];
  const float* W = (blockIdx.z==0)? W0 : (blockIdx.z==1)? W1 : W2;
  __half* Dhi = (blockIdx.z==0)? d_Whh0h : (blockIdx.z==1)? d_Wih1h : d_Whh1h;
  int c0 = blockIdx.x*64, k0 = blockIdx.y*64;
  int tx = threadIdx.x, ty = threadIdx.y;
  #pragma unroll
  for (int i=0;i<8;i++){
    int kl = ty + i*8;
    ts[kl][tx] = W[(size_t)(k0+kl)*Gn + c0 + tx];
  }
  __syncthreads();
  #pragma unroll
  for (int i=0;i<8;i++){
    int lc = ty + i*8;
    int c = c0 + lc;
    int q = c >> 10, jh = c & 1023;
    int pcol = ((q>>1)<<11) | (jh<<1) | (q&1);
    Dhi[(size_t)pcol*Hn + k0 + tx] = __float2half_rn(ts[tx][lc]);
  }
}

// ======== bvec/M2/b1 precompute (quad layout: jh*4+gate) ========
__global__ void k_prep(const float* __restrict__ Wih0, const float* __restrict__ bi,
                       const float* __restrict__ Wi,   const float* __restrict__ bih0,
                       const float* __restrict__ bhh0, const float* __restrict__ bih1,
                       const float* __restrict__ bhh1){
  int j = blockIdx.x*blockDim.x + threadIdx.x;
  float ab=0.f, a0=0.f, a1=0.f;
  for (int k=0;k<Hn;k++){
    float w = Wih0[(size_t)k*Gn + j];
    ab = fmaf(bi[k],    w, ab);
    a0 = fmaf(Wi[k],    w, a0);
    a1 = fmaf(Wi[Hn+k], w, a1);
  }
  int pcol = ((j & 1023) << 2) | (j >> 10);
  d_bvecM[pcol]        = bih0[j] + bhh0[j] + ab;
  d_bvecM[Gn+pcol]     = a0;
  d_bvecM[2*Gn+pcol]   = a1;
  d_b1p[pcol]          = bih1[j] + bhh1[j];
}

// ============ one-time fp32 GEMM (cond and condG0p) ============
#define AS_LD 132
template<int MODE>
__global__ __launch_bounds__(256) void gemm128(const float* __restrict__ Aext,
    const float* __restrict__ W, const float* __restrict__ biasExt, int N, int K)
{
  __shared__ float As[16*AS_LD];
  __shared__ float Ws[16*AS_LD];
  const int m0 = blockIdx.y*128, n0 = blockIdx.x*128;
  const int tid = threadIdx.x;
  const int trow = tid>>4, tcol = tid&15;
  float acc[8][8];
  #pragma unroll
  for(int i=0;i<8;i++){
    #pragma unroll
    for(int j=0;j<8;j++) acc[i][j]=0.f;
  }
  const float* Ap = MODE ? d_cond : Aext;
  for (int k0=0;k0<K;k0+=16){
    #pragma unroll
    for (int i=0;i<2;i++){
      int f = tid + i*256;
      int r = f>>2, c = f&3;
      float4 v = *(const float4*)(Ap + (size_t)(m0+r)*K + k0 + c*4);
      As[(c*4+0)*AS_LD + r]=v.x; As[(c*4+1)*AS_LD + r]=v.y;
      As[(c*4+2)*AS_LD + r]=v.z; As[(c*4+3)*AS_LD + r]=v.w;
    }
    #pragma unroll
    for (int i=0;i<2;i++){
      int f = tid + i*256;
      int kr = f>>5, nc = f&31;
      *(float4*)(&Ws[kr*AS_LD + nc*4]) = *(const float4*)(W + (size_t)(k0+kr)*N + n0 + nc*4);
    }
    __syncthreads();
    #pragma unroll
    for (int kk=0;kk<16;kk++){
      float a[8], b[8];
      *(float4*)(a)   = *(const float4*)(&As[kk*AS_LD + trow*8]);
      *(float4*)(a+4) = *(const float4*)(&As[kk*AS_LD + trow*8+4]);
      *(float4*)(b)   = *(const float4*)(&Ws[kk*AS_LD + tcol*8]);
      *(float4*)(b+4) = *(const float4*)(&Ws[kk*AS_LD + tcol*8+4]);
      #pragma unroll
      for(int i=0;i<8;i++){
        #pragma unroll
        for(int j=0;j<8;j++) acc[i][j] = fmaf(a[i], b[j], acc[i][j]);
      }
    }
    __syncthreads();
  }
  #pragma unroll
  for (int i=0;i<8;i++){
    int r = m0 + trow*8 + i;
    #pragma unroll
    for (int j=0;j<8;j++){
      int col = n0 + tcol*8 + j;
      float v = acc[i][j];
      if (MODE==0){
        v += biasExt[col];
        d_cond[(size_t)r*N + col] = v;
      } else {
        int pcol = ((col & 1023) << 2) | (col >> 10);
        v += d_bvecM[pcol];
        d_condG0p[(size_t)r*N + pcol] = v;
      }
    }
  }
}

// ============================ persistent step kernel ============================
#define STAGE_BYTES 65536
#define NSTAGE 3
#define SM_CUR (NSTAGE*STAGE_BYTES)
#define SM_WO  (SM_CUR + 1024)
#define SM_BO  (SM_WO + 4352)
#define GEMM_SMEM (SM_BO + 256)

__device__ __forceinline__ void load_stage(uint32_t sbase, const __half* Asrc,
    const __half* Whi, int m0, int nb, int k0, int tid){
  #pragma unroll
  for (int it=0; it<8; it++){
    int idx = it*NTHR + tid;
    int tile = idx >> 11;
    int rem  = idx & 2047;
    int row  = rem >> 4;
    int cc   = rem & 15;
    const __half* src;
    if (tile==0) src = Asrc + (size_t)(m0+row)*Hn;
    else {
      int pr = nb*64 + row + ((row>=64)? (2048-64) : 0);
      src = Whi + (size_t)pr*Hn;
    }
    uint32_t daddr = sbase + tile*32768 + row*256 + ((cc ^ (row&7))<<4);
    const void* g = (const void*)(src + k0 + cc*8);
    asm volatile("cp.async.cg.shared.global [%0], [%1], 16;" :: "r"(daddr), "l"(g));
  }
}

__device__ __forceinline__ void compute_stage(uint32_t sbase, float acc[2][4][4],
                                              int lane, int wm, int wn){
  const uint32_t As = sbase, Bh = sbase + 32768;
  #pragma unroll
  for (int kk=0; kk<8; kk++){
    uint32_t a[2][4];
    #pragma unroll
    for (int mt=0; mt<2; mt++){
      int m = wm*32 + mt*16 + (lane & 15);
      int ch = kk*2 + (lane>>4);
      uint32_t addr = As + m*256 + ((ch ^ (m&7))<<4);
      asm volatile("ldmatrix.sync.aligned.m8n8.x4.shared.b16 {%0,%1,%2,%3}, [%4];"
        : "=r"(a[mt][0]),"=r"(a[mt][1]),"=r"(a[mt][2]),"=r"(a[mt][3]) : "r"(addr));
    }
    uint32_t bh[4][2];
    #pragma unroll
    for (int np=0; np<2; np++){
      int mat = lane >> 3;
      int ntl = np*2 + (mat>>1);
      int ch  = kk*2 + (mat&1);
      int rb = (ntl<2 ? wn*16 + ntl*8 : 64 + wn*16 + (ntl-2)*8) + (lane&7);
      uint32_t addr = Bh + rb*256 + ((ch ^ (rb&7))<<4);
      uint32_t r0,r1,r2,r3;
      asm volatile("ldmatrix.sync.aligned.m8n8.x4.shared.b16 {%0,%1,%2,%3}, [%4];"
        : "=r"(r0),"=r"(r1),"=r"(r2),"=r"(r3) : "r"(addr));
      bh[np*2+0][0]=r0; bh[np*2+0][1]=r1;
      bh[np*2+1][0]=r2; bh[np*2+1][1]=r3;
    }
    #pragma unroll
    for (int mt=0; mt<2; mt++){
      #pragma unroll
      for (int nt=0; nt<4; nt++){
        MMA16816(acc[mt][nt], a[mt], bh[nt]);
      }
    }
  }
}

// L0: ch 0-7 = h0_prev@Whh0
// L1: ch 0-7 = h1_prev@Whh1 (hoistable), ch 8-15 = h0(s)@Wih1 (post-barrier)
template<int LAYER>
__device__ __forceinline__ void chunk_src(int sbuf, int ch, const __half*& A,
    const __half*& Wh, int& k0){
  if (LAYER==0){ A = d_h0h[sbuf^1]; Wh = d_Whh0h; k0 = ch*KC; }
  else if (ch < 8){ A = d_h1h[sbuf^1]; Wh = d_Whh1h; k0 = ch*KC; }
  else { A = d_h0h[sbuf]; Wh = d_Wih1h; k0 = (ch-8)*KC; }
}

// PROLOG_DONE: if 1, stages 0-1 were already filled+committed by caller
template<int LAYER, int PROLOG_DONE>
__device__ __forceinline__ void gemm_phase(char* smem, uint32_t sb, int sbuf, int nb, int m0,
    int tid, int lane, int wid, const float* curbuf, const float* wo_s, float* creg){
  const int wm = wid >> 2, wn = wid & 3;
  const int nch = LAYER ? 16 : 8;

  float acc[2][4][4];
  #pragma unroll
  for (int i=0;i<2;i++){
    #pragma unroll
    for (int j=0;j<4;j++){
      #pragma unroll
      for (int k=0;k<4;k++) acc[i][j][k]=0.f;
    }
  }

  if (!PROLOG_DONE){
    #pragma unroll
    for (int p=0;p<2;p++){
      const __half *A, *Wh; int k0;
      chunk_src<LAYER>(sbuf, p, A, Wh, k0);
      load_stage(sb + p*STAGE_BYTES, A, Wh, m0, nb, k0, tid);
      asm volatile("cp.async.commit_group;");
    }
  }
  for (int ch=0; ch<nch; ch++){
    asm volatile("cp.async.wait_group 1;");
    __syncthreads();
    if (ch+2 < nch){
      const __half *A, *Wh; int k0;
      chunk_src<LAYER>(sbuf, ch+2, A, Wh, k0);
      load_stage(sb + ((ch+2)%NSTAGE)*STAGE_BYTES, A, Wh, m0, nb, k0, tid);
    }
    asm volatile("cp.async.commit_group;");
    compute_stage(sb + (ch%NSTAGE)*STAGE_BYTES, acc, lane, wm, wn);
  }
  asm volatile("cp.async.wait_group 0;");
  __syncthreads();

  // ---- fused LSTM cell epilogue (warp: 32 rows x 32 cols), c in registers ----
  const int q  = lane & 3;
  const int tq = lane >> 2;
  __half* hout = LAYER ? d_h1h[sbuf] : d_h0h[sbuf];
  float* hbuf = (float*)smem;    // stage0 region reuse (L1 only)

  #pragma unroll
  for (int mt=0; mt<2; mt++){
    #pragma unroll
    for (int rr=0; rr<2; rr++){
      int lr = wm*32 + mt*16 + tq + rr*8;
      int r = m0 + lr;
      float cu0 = 0.f, cu1 = 0.f;
      if (LAYER == 0){ cu0 = curbuf[2*lr]; cu1 = curbuf[2*lr+1]; }
      #pragma unroll
      for (int nt=0; nt<2; nt++){
        int cloc = wn*8 + nt*4 + q;
        int jh = nb*32 + cloc;
        int ci = mt*4 + rr*2 + nt;
        float vi = acc[mt][nt  ][rr*2+0];
        float vf = acc[mt][nt  ][rr*2+1];
        float vg = acc[mt][nt+2][rr*2+0];
        float vo = acc[mt][nt+2][rr*2+1];
        if (LAYER == 0){
          float4 pg = *(const float4*)&d_condG0p[(size_t)r*Gn + jh*4];
          float4 ma = *(const float4*)&d_bvecM[Gn + jh*4];
          float4 mb = *(const float4*)&d_bvecM[2*Gn + jh*4];
          vi += pg.x + cu0*ma.x + cu1*mb.x;
          vf += pg.y + cu0*ma.y + cu1*mb.y;
          vg += pg.z + cu0*ma.z + cu1*mb.z;
          vo += pg.w + cu0*ma.w + cu1*mb.w;
        } else {
          float4 b1 = *(const float4*)&d_b1p[jh*4];
          vi += b1.x; vf += b1.y; vg += b1.z; vo += b1.w;
        }
        float cn = fast_sig(vf)*creg[ci] + fast_sig(vi)*fast_tanh(vg);
        creg[ci] = cn;
        float h = fast_sig(vo)*fast_tanh(cn);
        hout[(size_t)r*Hn + jh] = __float2half_rn(h);
        if (LAYER) hbuf[lr*33 + cloc] = h;
      }
    }
  }

  // ---- L1: partial logits over this CTA's 32 columns, int atomics ----
  if (LAYER == 1){
    __syncthreads();
    const int lr = tid >> 2, qt = tid & 3;   // 4 threads per row
    float pacc[NCn];
    #pragma unroll
    for (int c=0;c<NCn;c++) pacc[c]=0.f;
    const float* hb = hbuf + lr*33;
    #pragma unroll
    for (int cc2=0; cc2<8; cc2++){
      int col = qt*8 + cc2;
      float h = hb[col];
      const float* wr = wo_s + col*34;
      #pragma unroll
      for (int o=0;o<NCn;o++) pacc[o] = fmaf(h, wr[o], pacc[o]);
    }
    int* ob = &d_intbuf[sbuf][(m0+lr)*NCn];
    #pragma unroll
    for (int o=0;o<NCn;o++){
      float v = pacc[o];
      v += __shfl_xor_sync(0xffffffffu, v, 1);
      v += __shfl_xor_sync(0xffffffffu, v, 2);
      if (qt == 0) atomicAdd(&ob[o], __float2int_rn(v*LSCALE));
    }
  }
}

__global__ __launch_bounds__(NTHR, 1) void k_steps(const float* __restrict__ Wo,
    const float* __restrict__ bo, float* __restrict__ out){
  extern __shared__ char smem[];
  const uint32_t sb = smem_u32(smem);
  float* curbuf = (float*)(smem + SM_CUR);
  float* wo_s   = (float*)(smem + SM_WO);
  float* bos    = (float*)(smem + SM_BO);
  const int tid = threadIdx.x;
  const int lane = tid & 31, wid = tid >> 5;
  const int cta = blockIdx.x;
  const int nb = cta & 31, m0 = (cta >> 5) * 128;
  const int band = cta >> 5;

  for (int i=tid; i<32*NCn; i+=NTHR){
    int col = i/NCn, c = i - col*NCn;
    wo_s[col*34+c] = Wo[(size_t)(nb*32+col)*NCn + c];
  }
  if (tid < NCn) bos[tid] = bo[tid];
  __syncthreads();

  // register-resident cell state (this thread's 8 cells per layer, all steps)
  float c0r[8], c1r[8];
  #pragma unroll
  for (int i=0;i<8;i++){ c0r[i]=0.f; c1r[i]=0.f; }

  unsigned bar = 0;
  for (int s=0; s<NSTEPS; s++){
    const int sbuf = s & 1;
    // ---- cur compute for this band (warps 0-3) ----
    if (tid < 128){
      int r = m0 + tid;
      float cu0, cu1;
      if (s == 0){
        cu0 = d_cur[2*r]; cu1 = d_cur[2*r+1];
      } else {
        const int* ib = &d_intbuf[(s-1)&1][r*NCn];
        float lg0 = (float)ib[0]*LINV + bos[0];
        float best = -3.4e38f; int bidx = 0;
        #pragma unroll
        for (int c=1;c<NCn;c++){
          float v = (float)ib[c]*LINV + bos[c];
          if (v > best){ best = v; bidx = c-1; }
        }
        cu0 = (lg0 > 0.f) ? 1.f : 0.f;
        cu1 = (float)bidx * (1.f/(VBn-1));
      }
      curbuf[tid*2] = cu0; curbuf[tid*2+1] = cu1;
    }
    // ---- distributed out writes for step s-1 (warps 8-11, concurrent) ----
    if (s > 0 && tid >= 256 && tid < 388){
      int t2 = tid - 256;
      int r = m0 + nb*4 + t2/33;
      int c = t2 - (t2/33)*33;
      float v = (float)d_intbuf[(s-1)&1][r*NCn + c]*LINV + bos[c];
      int b = r>>6, tt = r&63;
      out[(((size_t)b*NCn + c)*64 + tt)*128 + (s-1)] = v;
    }
    __syncthreads();
    if (s == 0){
      gemm_phase<0,0>(smem, sb, sbuf, nb, m0, tid, lane, wid, curbuf, wo_s, c0r);
    } else {
      gemm_phase<0,1>(smem, sb, sbuf, nb, m0, tid, lane, wid, curbuf, wo_s, c0r);
    }

    // ---- hoisted L1 prologue (chunks 0-1 = h1_prev@Whh1; prev-step sources) ----
    #pragma unroll
    for (int p=0;p<2;p++){
      const __half *A, *Wh; int k0;
      chunk_src<1>(sbuf, p, A, Wh, k0);
      load_stage(sb + p*STAGE_BYTES, A, Wh, m0, nb, k0, tid);
      asm volatile("cp.async.commit_group;");
    }
    gridbar(band, ++bar);
    if (tid < 132) d_intbuf[sbuf ^ 1][cta*132 + tid] = 0;
    gemm_phase<1,1>(smem, sb, sbuf, nb, m0, tid, lane, wid, curbuf, wo_s, c1r);

    // ---- hoisted L0(s+1) prologue: sources synced at mid-step barrier ----
    if (s + 1 < NSTEPS){
      __syncthreads();   // all threads done reading hbuf (aliases stage 0)
      #pragma unroll
      for (int p=0;p<2;p++){
        const __half *A, *Wh; int k0;
        chunk_src<0>((s+1)&1, p, A, Wh, k0);
        load_stage(sb + p*STAGE_BYTES, A, Wh, m0, nb, k0, tid);
        asm volatile("cp.async.commit_group;");
      }
    }
    gridbar(band, ++bar);
  }
  // final out for s = 127 (distributed: 4 rows per CTA)
  if (tid < 132){
    int r = m0 + nb*4 + tid/33;
    int c = tid - (tid/33)*33;
    float v = (float)d_intbuf[1][r*NCn + c]*LINV + bos[c];
    int b = r>>6, tt = r&63;
    out[(((size_t)b*NCn + c)*64 + tt)*128 + 127] = v;
  }
}

// ============================ launch ============================
extern "C" void kernel_launch(void* const* d_in, const int* in_sizes, int n_in,
                              void* d_out, int out_size){
  const float* x    = (const float*)d_in[0];
  const float* sos  = (const float*)d_in[1];
  const float* Wc   = (const float*)d_in[2];
  const float* bc   = (const float*)d_in[3];
  const float* Wi   = (const float*)d_in[4];
  const float* bi   = (const float*)d_in[5];
  const float* Wih0 = (const float*)d_in[6];
  const float* Whh0 = (const float*)d_in[7];
  const float* bih0 = (const float*)d_in[8];
  const float* bhh0 = (const float*)d_in[9];
  const float* Wih1 = (const float*)d_in[10];
  const float* Whh1 = (const float*)d_in[11];
  const float* bih1 = (const float*)d_in[12];
  const float* bhh1 = (const float*)d_in[13];
  const float* Wo   = (const float*)d_in[14];
  const float* bo   = (const float*)d_in[15];
  float* out = (float*)d_out;

  cudaFuncSetAttribute(k_steps, cudaFuncAttributeMaxDynamicSharedMemorySize, GEMM_SMEM);

  k_init<<<(BTn*Hn+255)/256, 256>>>(sos);
  k_wconv<<<dim3(Gn/64, Hn/64, 3), dim3(64,8)>>>(Whh0, Wih1, Whh1);
  k_prep<<<Gn/128, 128>>>(Wih0, bi, Wi, bih0, bhh0, bih1, bhh1);
  gemm128<0><<<dim3(Hn/128, BTn/128), 256>>>(x, Wc, bc, Hn, En);
  gemm128<1><<<dim3(Gn/128, BTn/128), 256>>>(nullptr, Wih0 + (size_t)Hn*Gn, nullptr, Gn, Hn);

  k_steps<<<NCTA, NTHR, GEMM_SMEM>>>(Wo, bo, out);
}